// round 12
// baseline (speedup 1.0000x reference)
#include <cuda_runtime.h>

#define BB   4
#define NN   8000
#define CC   64
#define KK   32
#define DD   9
#define NCLS 13
#define BN   (BB*NN)

#define CAP   128         // per-thread candidate buffer slots (1KB local)
#define HALF  (NN/2)      // 4000 candidates per half-thread

__device__ float  g_G1[BN*CC];
__device__ float  g_G2[BN*CC];
__device__ float4 g_pts[BN];
__device__ int    g_idx[BN*KK];

__device__ __forceinline__ float inf_f() { return __int_as_float(0x7f800000); }

// ---------------------------------------------------------------------------
// Encoder (measured-best: block=256, 161 regs, ~101us):
// feats = relu(x@w1+b1)@w2+b2 ; G1 = feats@f1w ; G2 = feats@f2w
// ---------------------------------------------------------------------------
__global__ __launch_bounds__(256) void encoder_kernel(
    const float* __restrict__ x,
    const float* __restrict__ w1, const float* __restrict__ b1v,
    const float* __restrict__ w2, const float* __restrict__ b2v,
    const float* __restrict__ f1w, const float* __restrict__ f2w)
{
    int g = blockIdx.x * blockDim.x + threadIdx.x;
    if (g >= BN) return;

    float xr[DD];
    #pragma unroll
    for (int d = 0; d < DD; d++) xr[d] = x[g*DD + d];
    g_pts[g] = make_float4(xr[0], xr[1], xr[2],
                           xr[0]*xr[0] + xr[1]*xr[1] + xr[2]*xr[2]);

    float acc[CC];

    // hidden = relu(x @ w1 + b1)
    {
        const float4* bq = (const float4*)b1v;
        #pragma unroll
        for (int c4 = 0; c4 < CC/4; c4++) {
            float4 bv = bq[c4];
            acc[c4*4+0]=bv.x; acc[c4*4+1]=bv.y; acc[c4*4+2]=bv.z; acc[c4*4+3]=bv.w;
        }
        #pragma unroll
        for (int d = 0; d < DD; d++) {
            float xv = xr[d];
            const float4* wv = (const float4*)(w1 + d*CC);
            #pragma unroll
            for (int c4 = 0; c4 < CC/4; c4++) {
                float4 w = wv[c4];
                acc[c4*4+0] = fmaf(xv, w.x, acc[c4*4+0]);
                acc[c4*4+1] = fmaf(xv, w.y, acc[c4*4+1]);
                acc[c4*4+2] = fmaf(xv, w.z, acc[c4*4+2]);
                acc[c4*4+3] = fmaf(xv, w.w, acc[c4*4+3]);
            }
        }
    }
    float hloc[CC];
    #pragma unroll
    for (int c = 0; c < CC; c++) hloc[c] = fmaxf(acc[c], 0.f);

    // feats = hidden @ w2 + b2
    {
        const float4* bq = (const float4*)b2v;
        #pragma unroll
        for (int c4 = 0; c4 < CC/4; c4++) {
            float4 bv = bq[c4];
            acc[c4*4+0]=bv.x; acc[c4*4+1]=bv.y; acc[c4*4+2]=bv.z; acc[c4*4+3]=bv.w;
        }
        #pragma unroll 1
        for (int j = 0; j < CC; j++) {
            float hv = hloc[j];
            const float4* wv = (const float4*)(w2 + j*CC);
            #pragma unroll
            for (int c4 = 0; c4 < CC/4; c4++) {
                float4 w = wv[c4];
                acc[c4*4+0] = fmaf(hv, w.x, acc[c4*4+0]);
                acc[c4*4+1] = fmaf(hv, w.y, acc[c4*4+1]);
                acc[c4*4+2] = fmaf(hv, w.z, acc[c4*4+2]);
                acc[c4*4+3] = fmaf(hv, w.w, acc[c4*4+3]);
            }
        }
    }
    float floc[CC];
    #pragma unroll
    for (int c = 0; c < CC; c++) floc[c] = acc[c];

    // G1 = feats @ f1w
    #pragma unroll
    for (int c = 0; c < CC; c++) acc[c] = 0.f;
    #pragma unroll 1
    for (int j = 0; j < CC; j++) {
        float fv = floc[j];
        const float4* wv = (const float4*)(f1w + j*CC);
        #pragma unroll
        for (int c4 = 0; c4 < CC/4; c4++) {
            float4 w = wv[c4];
            acc[c4*4+0] = fmaf(fv, w.x, acc[c4*4+0]);
            acc[c4*4+1] = fmaf(fv, w.y, acc[c4*4+1]);
            acc[c4*4+2] = fmaf(fv, w.z, acc[c4*4+2]);
            acc[c4*4+3] = fmaf(fv, w.w, acc[c4*4+3]);
        }
    }
    {
        float4* o = (float4*)g_G1 + g*(CC/4);
        #pragma unroll
        for (int c4 = 0; c4 < CC/4; c4++)
            o[c4] = make_float4(acc[c4*4+0], acc[c4*4+1], acc[c4*4+2], acc[c4*4+3]);
    }

    // G2 = feats @ f2w
    #pragma unroll
    for (int c = 0; c < CC; c++) acc[c] = 0.f;
    #pragma unroll 1
    for (int j = 0; j < CC; j++) {
        float fv = floc[j];
        const float4* wv = (const float4*)(f2w + j*CC);
        #pragma unroll
        for (int c4 = 0; c4 < CC/4; c4++) {
            float4 w = wv[c4];
            acc[c4*4+0] = fmaf(fv, w.x, acc[c4*4+0]);
            acc[c4*4+1] = fmaf(fv, w.y, acc[c4*4+1]);
            acc[c4*4+2] = fmaf(fv, w.z, acc[c4*4+2]);
            acc[c4*4+3] = fmaf(fv, w.w, acc[c4*4+3]);
        }
    }
    {
        float4* o = (float4*)g_G2 + g*(CC/4);
        #pragma unroll
        for (int c4 = 0; c4 < CC/4; c4++)
            o[c4] = make_float4(acc[c4*4+0], acc[c4*4+1], acc[c4*4+2], acc[c4*4+3]);
    }
}

// ---------------------------------------------------------------------------
// Exact 32-smallest of buf[0..cnt) via 8x4 group-max insert (first-seen kept
// among equals). Writes survivors to buf[0..32); returns worst (32nd).
// ---------------------------------------------------------------------------
__device__ __noinline__ float compact32(unsigned long long* buf, int cnt,
                                        float* kd, int* ki)
{
    const float INF = inf_f();
    float gm[8];
    #pragma unroll
    for (int i = 0; i < 8; i++) gm[i] = INF;
    #pragma unroll 1
    for (int i = 0; i < KK; i++) { kd[i] = INF; ki[i] = 0; }
    float worst = INF;

    #pragma unroll 1
    for (int tix = 0; tix < cnt; tix++) {
        unsigned long long v = buf[tix];
        float s = __uint_as_float((unsigned)(v >> 32));
        if (s < worst) {
            int id = (int)(unsigned)v;
            int gsel = 0; float gv = gm[0];
            #pragma unroll
            for (int i = 1; i < 8; i++) if (gm[i] > gv) { gv = gm[i]; gsel = i; }
            int base = gsel*4;
            float v0 = kd[base], v1 = kd[base+1], v2 = kd[base+2], v3 = kd[base+3];
            int e = 0; float ev = v0;
            if (v1 > ev) { ev = v1; e = 1; }
            if (v2 > ev) { ev = v2; e = 2; }
            if (v3 > ev) { ev = v3; e = 3; }
            kd[base+e] = s; ki[base+e] = id;
            float ngm = fmaxf(fmaxf(e==0?s:v0, e==1?s:v1),
                              fmaxf(e==2?s:v2, e==3?s:v3));
            #pragma unroll
            for (int i = 0; i < 8; i++) if (i == gsel) gm[i] = ngm;
            float w8 = gm[0];
            #pragma unroll
            for (int i = 1; i < 8; i++) w8 = fmaxf(w8, gm[i]);
            worst = w8;
        }
    }
    #pragma unroll 1
    for (int i = 0; i < KK; i++)
        buf[i] = ((unsigned long long)__float_as_uint(kd[i]) << 32) |
                 (unsigned)ki[i];
    return worst;
}

// ---------------------------------------------------------------------------
// Exact 32-NN, 2 threads per query (512-thread blocks -> 16 warps/SM instead
// of 8; grid still 128 blocks = 1 block/SM). Thread (qs, h) scans half h of
// the candidates with the proven thr-from-INF + tree-prefix predicated-append
// + warp-synchronized-compaction machinery (h = tid>>8 is warp-uniform, so
// __any_sync stays warp-uniform). Halves exchange their exact half-top-32
// through reused smem; half 0 compacts the 64-entry union -> exact global
// top-32 (any global winner is in its half's top-32).
// ---------------------------------------------------------------------------
__global__ __launch_bounds__(512) void knn_kernel() {
    extern __shared__ float4 sp[];
    unsigned long long* sm64 = (unsigned long long*)sp;
    int b = blockIdx.y;
    for (int j = threadIdx.x; j < NN; j += 512) sp[j] = g_pts[b*NN + j];
    __syncthreads();

    int tid = threadIdx.x;
    int qs = tid & 255;                   // query slot within block
    int h  = tid >> 8;                    // half (0/1), warp-uniform
    int q = blockIdx.x * 256 + qs;
    if (q >= NN) q = NN - 1;              // clamp (ballot safety)

    float4 me = sp[q];
    float mx = -2.f*me.x, my = -2.f*me.y, mz = -2.f*me.z;
    const float INF = inf_f();

    unsigned long long buf[CAP];
    float kd[KK]; int ki[KK];
    float thr = INF;
    int cnt = 0;
    int jb = h * HALF;

    #pragma unroll 1
    for (int jo = 0; jo < HALF/32; jo++) {   // 125 outer iterations
        #pragma unroll 1
        for (int gi = 0; gi < 4; gi++) {
            int j0 = jb + jo*32 + gi*8;
            float s[8];
            #pragma unroll
            for (int u = 0; u < 8; u++) {
                float4 c = sp[j0 + u];
                float ss = fmaf(c.x, mx, c.w);
                ss = fmaf(c.y, my, ss);
                s[u] = fmaf(c.z, mz, ss);
            }
            // predicates + tree-prefix offsets (independent stores)
            int e0 = (s[0] < thr) ? 1 : 0;
            int e1 = (s[1] < thr) ? 1 : 0;
            int e2 = (s[2] < thr) ? 1 : 0;
            int e3 = (s[3] < thr) ? 1 : 0;
            int e4 = (s[4] < thr) ? 1 : 0;
            int e5 = (s[5] < thr) ? 1 : 0;
            int e6 = (s[6] < thr) ? 1 : 0;
            int e7 = (s[7] < thr) ? 1 : 0;
            int t01 = e0 + e1, t23 = e2 + e3, t45 = e4 + e5, t67 = e6 + e7;
            int t03 = t01 + t23, t47 = t45 + t67;
            int o1 = e0;
            int o2 = t01;
            int o3 = t01 + e2;
            int o4 = t03;
            int o5 = t03 + e4;
            int o6 = t03 + t45;
            int o7 = t03 + t45 + e6;
            int tot = t03 + t47;
            #pragma unroll
            for (int u = 0; u < 8; u++) {
                int off;
                switch (u) {               // compile-time resolved
                    case 0: off = 0;  break;
                    case 1: off = o1; break;
                    case 2: off = o2; break;
                    case 3: off = o3; break;
                    case 4: off = o4; break;
                    case 5: off = o5; break;
                    case 6: off = o6; break;
                    default: off = o7; break;
                }
                unsigned long long pk =
                    ((unsigned long long)__float_as_uint(s[u]) << 32)
                    | (unsigned)(j0 + u);
                if (s[u] < thr) buf[cnt + off] = pk;   // @P STL.64
            }
            cnt += tot;
        }
        if (__any_sync(0xffffffffu, cnt >= CAP - 32)) {
            float w2 = compact32(buf, cnt, kd, ki);
            thr = fminf(thr, w2);
            cnt = KK;
        }
    }

    compact32(buf, cnt, kd, ki);           // exact half-top-32 in buf[0..32)

    // exchange halves through reused smem (scan reads of sp are all done)
    __syncthreads();
    {
        unsigned long long* dst = sm64 + (qs*2 + h)*KK;
        #pragma unroll 1
        for (int i = 0; i < KK; i++) dst[i] = buf[i];
    }
    __syncthreads();

    if (h == 0) {
        const unsigned long long* part = sm64 + (qs*2 + 1)*KK;
        #pragma unroll 1
        for (int i = 0; i < KK; i++) buf[KK + i] = part[i];
        compact32(buf, 2*KK, kd, ki);      // exact global top-32
        int* o = g_idx + (b*NN + q)*KK;
        #pragma unroll 1
        for (int i = 0; i < KK; i++) o[i] = ki[i];
    }
}

// ---------------------------------------------------------------------------
// Fuse (both branches) + classifier. msg = relu(G[nbr]-G[i]+b); max over K;
// fused = m1+m2; then 64->32->13 MLP. 4 points/block, 64 channel-threads.
// ---------------------------------------------------------------------------
__global__ __launch_bounds__(256) void fuse_kernel(
    const float* __restrict__ f1b, const float* __restrict__ f2b,
    const float* __restrict__ cw1, const float* __restrict__ cb1,
    const float* __restrict__ cw2, const float* __restrict__ cb2,
    float* __restrict__ out)
{
    __shared__ float sfused[4][CC];
    __shared__ float shid[4][CC/2];
    __shared__ int   sidx[4][KK];

    int tid = threadIdx.x;
    int p = tid >> 6, c = tid & 63;
    int g = blockIdx.x*4 + p;

    if (c < KK) sidx[p][c] = g_idx[g*KK + c];
    __syncthreads();

    int b = g / NN;
    int rowbase = b*NN;

    float g1i = g_G1[g*CC + c];
    float g2i = g_G2[g*CC + c];
    float bb1 = f1b[c] - g1i;
    float bb2 = f2b[c] - g2i;
    float m1 = 0.f, m2 = 0.f;
    #pragma unroll 8
    for (int k = 0; k < KK; k++) {
        int j = sidx[p][k] + rowbase;
        m1 = fmaxf(m1, g_G1[j*CC + c] + bb1);
        m2 = fmaxf(m2, g_G2[j*CC + c] + bb2);
    }
    sfused[p][c] = m1 + m2;
    __syncthreads();

    if (c < CC/2) {
        float a = cb1[c];
        #pragma unroll
        for (int u = 0; u < CC; u++) a = fmaf(sfused[p][u], cw1[u*(CC/2) + c], a);
        shid[p][c] = fmaxf(a, 0.f);
    }
    __syncthreads();

    if (c < NCLS) {
        float a = cb2[c];
        #pragma unroll
        for (int u = 0; u < CC/2; u++) a = fmaf(shid[p][u], cw2[u*NCLS + c], a);
        out[g*NCLS + c] = a;
    }
}

extern "C" void kernel_launch(void* const* d_in, const int* in_sizes, int n_in,
                              void* d_out, int out_size) {
    const float* x      = (const float*)d_in[0];
    const float* enc_w1 = (const float*)d_in[1];
    const float* enc_b1 = (const float*)d_in[2];
    const float* enc_w2 = (const float*)d_in[3];
    const float* enc_b2 = (const float*)d_in[4];
    const float* f1_w   = (const float*)d_in[5];
    const float* f1_b   = (const float*)d_in[6];
    const float* f2_w   = (const float*)d_in[7];
    const float* f2_b   = (const float*)d_in[8];
    const float* cls_w1 = (const float*)d_in[9];
    const float* cls_b1 = (const float*)d_in[10];
    const float* cls_w2 = (const float*)d_in[11];
    const float* cls_b2 = (const float*)d_in[12];

    encoder_kernel<<<(BN + 255)/256, 256>>>(x, enc_w1, enc_b1, enc_w2, enc_b2,
                                            f1_w, f2_w);

    // smem: max(candidates 8000*16 = 128000, merge 256*2*32*8 = 131072)
    const int knn_smem = 131072;
    cudaFuncSetAttribute(knn_kernel, cudaFuncAttributeMaxDynamicSharedMemorySize,
                         knn_smem);
    dim3 kg((NN + 255)/256, BB);
    knn_kernel<<<kg, 512, knn_smem>>>();

    fuse_kernel<<<BN/4, 256>>>(f1_b, f2_b, cls_w1, cls_b1, cls_w2, cls_b2,
                               (float*)d_out);
}

// round 13
// speedup vs baseline: 1.5416x; 1.5416x over previous
#include <cuda_runtime.h>

#define BB   4
#define NN   8000
#define CC   64
#define KK   32
#define DD   9
#define NCLS 13
#define BN   (BB*NN)

#define CHUNK 2000        // candidates per smem chunk (32KB), 4 chunks
#define CAP   56          // append slots per thread (smem)
#define NSLOT (KK + CAP)  // 88 u64 slots per thread
// smem: 32768 (chunk) + 88*256*8 = 180224  -> 212992 B total

__device__ float  g_G1[BN*CC];
__device__ float  g_G2[BN*CC];
__device__ float4 g_pts[BN];
__device__ int    g_idx[BN*KK];

__device__ __forceinline__ float inf_f() { return __int_as_float(0x7f800000); }

// ---------------------------------------------------------------------------
// Encoder (measured-best: block=256, 161 regs, ~101us):
// feats = relu(x@w1+b1)@w2+b2 ; G1 = feats@f1w ; G2 = feats@f2w
// ---------------------------------------------------------------------------
__global__ __launch_bounds__(256) void encoder_kernel(
    const float* __restrict__ x,
    const float* __restrict__ w1, const float* __restrict__ b1v,
    const float* __restrict__ w2, const float* __restrict__ b2v,
    const float* __restrict__ f1w, const float* __restrict__ f2w)
{
    int g = blockIdx.x * blockDim.x + threadIdx.x;
    if (g >= BN) return;

    float xr[DD];
    #pragma unroll
    for (int d = 0; d < DD; d++) xr[d] = x[g*DD + d];
    g_pts[g] = make_float4(xr[0], xr[1], xr[2],
                           xr[0]*xr[0] + xr[1]*xr[1] + xr[2]*xr[2]);

    float acc[CC];

    // hidden = relu(x @ w1 + b1)
    {
        const float4* bq = (const float4*)b1v;
        #pragma unroll
        for (int c4 = 0; c4 < CC/4; c4++) {
            float4 bv = bq[c4];
            acc[c4*4+0]=bv.x; acc[c4*4+1]=bv.y; acc[c4*4+2]=bv.z; acc[c4*4+3]=bv.w;
        }
        #pragma unroll
        for (int d = 0; d < DD; d++) {
            float xv = xr[d];
            const float4* wv = (const float4*)(w1 + d*CC);
            #pragma unroll
            for (int c4 = 0; c4 < CC/4; c4++) {
                float4 w = wv[c4];
                acc[c4*4+0] = fmaf(xv, w.x, acc[c4*4+0]);
                acc[c4*4+1] = fmaf(xv, w.y, acc[c4*4+1]);
                acc[c4*4+2] = fmaf(xv, w.z, acc[c4*4+2]);
                acc[c4*4+3] = fmaf(xv, w.w, acc[c4*4+3]);
            }
        }
    }
    float hloc[CC];
    #pragma unroll
    for (int c = 0; c < CC; c++) hloc[c] = fmaxf(acc[c], 0.f);

    // feats = hidden @ w2 + b2
    {
        const float4* bq = (const float4*)b2v;
        #pragma unroll
        for (int c4 = 0; c4 < CC/4; c4++) {
            float4 bv = bq[c4];
            acc[c4*4+0]=bv.x; acc[c4*4+1]=bv.y; acc[c4*4+2]=bv.z; acc[c4*4+3]=bv.w;
        }
        #pragma unroll 1
        for (int j = 0; j < CC; j++) {
            float hv = hloc[j];
            const float4* wv = (const float4*)(w2 + j*CC);
            #pragma unroll
            for (int c4 = 0; c4 < CC/4; c4++) {
                float4 w = wv[c4];
                acc[c4*4+0] = fmaf(hv, w.x, acc[c4*4+0]);
                acc[c4*4+1] = fmaf(hv, w.y, acc[c4*4+1]);
                acc[c4*4+2] = fmaf(hv, w.z, acc[c4*4+2]);
                acc[c4*4+3] = fmaf(hv, w.w, acc[c4*4+3]);
            }
        }
    }
    float floc[CC];
    #pragma unroll
    for (int c = 0; c < CC; c++) floc[c] = acc[c];

    // G1 = feats @ f1w
    #pragma unroll
    for (int c = 0; c < CC; c++) acc[c] = 0.f;
    #pragma unroll 1
    for (int j = 0; j < CC; j++) {
        float fv = floc[j];
        const float4* wv = (const float4*)(f1w + j*CC);
        #pragma unroll
        for (int c4 = 0; c4 < CC/4; c4++) {
            float4 w = wv[c4];
            acc[c4*4+0] = fmaf(fv, w.x, acc[c4*4+0]);
            acc[c4*4+1] = fmaf(fv, w.y, acc[c4*4+1]);
            acc[c4*4+2] = fmaf(fv, w.z, acc[c4*4+2]);
            acc[c4*4+3] = fmaf(fv, w.w, acc[c4*4+3]);
        }
    }
    {
        float4* o = (float4*)g_G1 + g*(CC/4);
        #pragma unroll
        for (int c4 = 0; c4 < CC/4; c4++)
            o[c4] = make_float4(acc[c4*4+0], acc[c4*4+1], acc[c4*4+2], acc[c4*4+3]);
    }

    // G2 = feats @ f2w
    #pragma unroll
    for (int c = 0; c < CC; c++) acc[c] = 0.f;
    #pragma unroll 1
    for (int j = 0; j < CC; j++) {
        float fv = floc[j];
        const float4* wv = (const float4*)(f2w + j*CC);
        #pragma unroll
        for (int c4 = 0; c4 < CC/4; c4++) {
            float4 w = wv[c4];
            acc[c4*4+0] = fmaf(fv, w.x, acc[c4*4+0]);
            acc[c4*4+1] = fmaf(fv, w.y, acc[c4*4+1]);
            acc[c4*4+2] = fmaf(fv, w.z, acc[c4*4+2]);
            acc[c4*4+3] = fmaf(fv, w.w, acc[c4*4+3]);
        }
    }
    {
        float4* o = (float4*)g_G2 + g*(CC/4);
        #pragma unroll
        for (int c4 = 0; c4 < CC/4; c4++)
            o[c4] = make_float4(acc[c4*4+0], acc[c4*4+1], acc[c4*4+2], acc[c4*4+3]);
    }
}

// ---------------------------------------------------------------------------
// Compaction: insert append-slots [KK, KK+cnt) into the 32 smem result slots
// (8 groups x 4, group-maxes in regs). Values are packed u64
// (dist_bits<<32 | idx); distances are true squared distances clamped >= 0,
// so u64 order == (dist, idx) lexicographic order == jax top_k order.
// ---------------------------------------------------------------------------
__device__ __forceinline__ void compact_smem(
    unsigned long long* tslot,   // &slots[tid], stride 256 per slot
    int& cnt, unsigned long long gm[8], unsigned long long& worst,
    float& thr)
{
    #pragma unroll 1
    for (int a = 0; a < cnt; a++) {
        unsigned long long v = tslot[(KK + a) * 256];
        if (v < worst) {
            int gsel = 0; unsigned long long gv = gm[0];
            #pragma unroll
            for (int i = 1; i < 8; i++) if (gm[i] > gv) { gv = gm[i]; gsel = i; }
            int base = gsel * 4;
            unsigned long long s0 = tslot[(base+0)*256];
            unsigned long long s1 = tslot[(base+1)*256];
            unsigned long long s2 = tslot[(base+2)*256];
            unsigned long long s3 = tslot[(base+3)*256];
            int e = 0; unsigned long long ev = s0;
            if (s1 > ev) { ev = s1; e = 1; }
            if (s2 > ev) { ev = s2; e = 2; }
            if (s3 > ev) { ev = s3; e = 3; }
            tslot[(base+e)*256] = v;
            unsigned long long n0 = (e==0)?v:s0, n1 = (e==1)?v:s1;
            unsigned long long n2 = (e==2)?v:s2, n3 = (e==3)?v:s3;
            unsigned long long m01 = n0 > n1 ? n0 : n1;
            unsigned long long m23 = n2 > n3 ? n2 : n3;
            unsigned long long ngm = m01 > m23 ? m01 : m23;
            #pragma unroll
            for (int i = 0; i < 8; i++) if (i == gsel) gm[i] = ngm;
            unsigned long long w8 = gm[0];
            #pragma unroll
            for (int i = 1; i < 8; i++) if (gm[i] > w8) w8 = gm[i];
            worst = w8;
        }
    }
    cnt = 0;
    thr = (worst == ~0ull) ? inf_f()
                           : __uint_as_float((unsigned)(worst >> 32));
}

// ---------------------------------------------------------------------------
// Exact 32-NN with ALL per-thread state in smem/registers (zero local memory
// in the hot path). Candidates stream through a 32KB smem chunk; per-thread
// 88-slot u64 buffers live in smem (strided, conflict-free). dist = true
// squared distance (clamped >= 0) packed with idx -> exact top_k semantics
// including lowest-index tie-breaks. thr=INF until the result slots fill;
// appends use <= so boundary ties survive. Compaction warp-synchronized.
// ---------------------------------------------------------------------------
__global__ __launch_bounds__(256) void knn_kernel() {
    extern __shared__ char smemraw[];
    float4* sp = (float4*)smemraw;
    unsigned long long* slots = (unsigned long long*)(smemraw + CHUNK*16);

    int tid = threadIdx.x;
    int b = blockIdx.y;
    const float4* src = g_pts + b*NN;

    int q = blockIdx.x * 256 + tid;
    if (q >= NN) q = NN - 1;              // clamp (ballot safety)

    float4 me = g_pts[b*NN + q];
    float qw = me.w;
    float mx = -2.f*me.x, my = -2.f*me.y, mz = -2.f*me.z;
    const float INF = inf_f();

    unsigned long long* tslot = slots + tid;
    // 32-bit smem address of append region base (slot KK) for this thread
    unsigned abase0;
    {
        const void* p = (const void*)(tslot + KK*256);
        unsigned long long l64;
        asm("cvta.to.shared.u64 %0, %1;" : "=l"(l64) : "l"(p));
        abase0 = (unsigned)l64;
    }

    // init result slots to +inf packed
    #pragma unroll
    for (int i = 0; i < KK; i++) tslot[i*256] = ~0ull;

    unsigned long long gm[8];
    #pragma unroll
    for (int i = 0; i < 8; i++) gm[i] = ~0ull;
    unsigned long long worst = ~0ull;
    float thr = INF;
    int cnt = 0;

    #pragma unroll 1
    for (int ch = 0; ch < NN/CHUNK; ch++) {          // 4 chunks
        __syncthreads();
        {
            const float4* csrc = src + ch*CHUNK;
            #pragma unroll
            for (int k = 0; k < CHUNK/256; k++)      // 7 rounds
                sp[tid + k*256] = csrc[tid + k*256];
            int j = tid + (CHUNK/256)*256;           // remainder (208)
            if (j < CHUNK) sp[j] = csrc[j];
        }
        __syncthreads();

        int jb = ch*CHUNK;
        #pragma unroll 1
        for (int jo = 0; jo < CHUNK/40; jo++) {      // 50 rounds x 40 cands
            #pragma unroll 1
            for (int gi = 0; gi < 5; gi++) {
                int j0 = jo*40 + gi*8;
                float s[8];
                #pragma unroll
                for (int u = 0; u < 8; u++) {
                    float4 c = sp[j0 + u];
                    float t0 = c.w + qw;             // |pj|^2 + |pi|^2
                    float ss = fmaf(c.x, mx, t0);
                    ss = fmaf(c.y, my, ss);
                    ss = fmaf(c.z, mz, ss);
                    s[u] = fmaxf(ss, 0.f);           // true sq-dist, >= 0
                }
                int e0 = (s[0] <= thr) ? 1 : 0;
                int e1 = (s[1] <= thr) ? 1 : 0;
                int e2 = (s[2] <= thr) ? 1 : 0;
                int e3 = (s[3] <= thr) ? 1 : 0;
                int e4 = (s[4] <= thr) ? 1 : 0;
                int e5 = (s[5] <= thr) ? 1 : 0;
                int e6 = (s[6] <= thr) ? 1 : 0;
                int e7 = (s[7] <= thr) ? 1 : 0;
                int t01 = e0+e1, t23 = e2+e3, t45 = e4+e5, t67 = e6+e7;
                int t03 = t01+t23, t47 = t45+t67;
                int o1 = e0, o2 = t01, o3 = t01+e2, o4 = t03;
                int o5 = t03+e4, o6 = t03+t45, o7 = t03+t45+e6;
                int tot = t03 + t47;
                unsigned rowa = abase0 + (unsigned)cnt * 2048u;
                #pragma unroll
                for (int u = 0; u < 8; u++) {
                    int off;
                    switch (u) {
                        case 0: off = 0;  break;
                        case 1: off = o1; break;
                        case 2: off = o2; break;
                        case 3: off = o3; break;
                        case 4: off = o4; break;
                        case 5: off = o5; break;
                        case 6: off = o6; break;
                        default: off = o7; break;
                    }
                    unsigned addr = rowa + (unsigned)off * 2048u;
                    unsigned long long pk =
                        ((unsigned long long)__float_as_uint(s[u]) << 32)
                        | (unsigned)(jb + j0 + u);
                    asm volatile(
                        "{\n\t"
                        ".reg .pred p;\n\t"
                        "setp.le.f32 p, %0, %1;\n\t"
                        "@p st.shared.b64 [%2], %3;\n\t"
                        "}"
                        :: "f"(s[u]), "f"(thr), "r"(addr), "l"(pk)
                        : "memory");
                }
                cnt += tot;
            }
            // margin: cnt <= 15 at check -> max 55 appends used (< CAP=56)
            if (__any_sync(0xffffffffu, cnt >= CAP - 40)) {
                compact_smem(tslot, cnt, gm, worst, thr);
            }
        }
    }

    compact_smem(tslot, cnt, gm, worst, thr);   // final flush (warp-uniform)

    int* o = g_idx + (b*NN + q)*KK;
    #pragma unroll 1
    for (int i = 0; i < KK; i++)
        o[i] = (int)(unsigned)tslot[i*256];
}

// ---------------------------------------------------------------------------
// Fuse (both branches) + classifier. msg = relu(G[nbr]-G[i]+b); max over K;
// fused = m1+m2; then 64->32->13 MLP. 4 points/block, 64 channel-threads.
// ---------------------------------------------------------------------------
__global__ __launch_bounds__(256) void fuse_kernel(
    const float* __restrict__ f1b, const float* __restrict__ f2b,
    const float* __restrict__ cw1, const float* __restrict__ cb1,
    const float* __restrict__ cw2, const float* __restrict__ cb2,
    float* __restrict__ out)
{
    __shared__ float sfused[4][CC];
    __shared__ float shid[4][CC/2];
    __shared__ int   sidx[4][KK];

    int tid = threadIdx.x;
    int p = tid >> 6, c = tid & 63;
    int g = blockIdx.x*4 + p;

    if (c < KK) sidx[p][c] = g_idx[g*KK + c];
    __syncthreads();

    int b = g / NN;
    int rowbase = b*NN;

    float g1i = g_G1[g*CC + c];
    float g2i = g_G2[g*CC + c];
    float bb1 = f1b[c] - g1i;
    float bb2 = f2b[c] - g2i;
    float m1 = 0.f, m2 = 0.f;
    #pragma unroll 8
    for (int k = 0; k < KK; k++) {
        int j = sidx[p][k] + rowbase;
        m1 = fmaxf(m1, g_G1[j*CC + c] + bb1);
        m2 = fmaxf(m2, g_G2[j*CC + c] + bb2);
    }
    sfused[p][c] = m1 + m2;
    __syncthreads();

    if (c < CC/2) {
        float a = cb1[c];
        #pragma unroll
        for (int u = 0; u < CC; u++) a = fmaf(sfused[p][u], cw1[u*(CC/2) + c], a);
        shid[p][c] = fmaxf(a, 0.f);
    }
    __syncthreads();

    if (c < NCLS) {
        float a = cb2[c];
        #pragma unroll
        for (int u = 0; u < CC/2; u++) a = fmaf(shid[p][u], cw2[u*NCLS + c], a);
        out[g*NCLS + c] = a;
    }
}

extern "C" void kernel_launch(void* const* d_in, const int* in_sizes, int n_in,
                              void* d_out, int out_size) {
    const float* x      = (const float*)d_in[0];
    const float* enc_w1 = (const float*)d_in[1];
    const float* enc_b1 = (const float*)d_in[2];
    const float* enc_w2 = (const float*)d_in[3];
    const float* enc_b2 = (const float*)d_in[4];
    const float* f1_w   = (const float*)d_in[5];
    const float* f1_b   = (const float*)d_in[6];
    const float* f2_w   = (const float*)d_in[7];
    const float* f2_b   = (const float*)d_in[8];
    const float* cls_w1 = (const float*)d_in[9];
    const float* cls_b1 = (const float*)d_in[10];
    const float* cls_w2 = (const float*)d_in[11];
    const float* cls_b2 = (const float*)d_in[12];

    encoder_kernel<<<(BN + 255)/256, 256>>>(x, enc_w1, enc_b1, enc_w2, enc_b2,
                                            f1_w, f2_w);

    const int knn_smem = CHUNK*16 + NSLOT*256*8;   // 32768 + 180224 = 212992
    cudaFuncSetAttribute(knn_kernel, cudaFuncAttributeMaxDynamicSharedMemorySize,
                         knn_smem);
    dim3 kg((NN + 255)/256, BB);
    knn_kernel<<<kg, 256, knn_smem>>>();

    fuse_kernel<<<BN/4, 256>>>(f1_b, f2_b, cls_w1, cls_b1, cls_w2, cls_b2,
                               (float*)d_out);
}

// round 14
// speedup vs baseline: 1.6376x; 1.0623x over previous
#include <cuda_runtime.h>

#define BB   4
#define NN   8000
#define CC   64
#define KK   32
#define DD   9
#define NCLS 13
#define BN   (BB*NN)

#define CHUNK 2000        // candidates per smem chunk (32KB SoA), 4 chunks
#define CAP   56          // append slots per thread (smem)
#define NSLOT (KK + CAP)  // 88 u64 slots per thread

__device__ float  g_G1[BN*CC];
__device__ float  g_G2[BN*CC];
__device__ float4 g_pts[BN];
__device__ int    g_idx[BN*KK];
__device__ float  g_C1[CC*CC], g_C2[CC*CC], g_c1[CC], g_c2[CC];

__device__ __forceinline__ float inf_f() { return __int_as_float(0x7f800000); }

#define FMA2(d,a,b,c) asm("fma.rn.f32x2 %0, %1, %2, %3;" : "=l"(d) : "l"(a), "l"(b), "l"(c))
#define ADD2(d,a,b)   asm("add.rn.f32x2 %0, %1, %2;" : "=l"(d) : "l"(a), "l"(b))
#define PK2(d,lo,hi)  asm("mov.b64 %0, {%1, %2};" : "=l"(d) : "f"(lo), "f"(hi))
#define UPK2(lo,hi,d) asm("mov.b64 {%0, %1}, %2;" : "=f"(lo), "=f"(hi) : "l"(d))

// ---------------------------------------------------------------------------
// Precompute: C1 = w2@f1w, C2 = w2@f2w, c1 = b2@f1w, c2 = b2@f2w.
// Lets the encoder skip the feats layer: G = hidden@C + c.
// ---------------------------------------------------------------------------
__global__ __launch_bounds__(256) void precompute_kernel(
    const float* __restrict__ w2, const float* __restrict__ b2v,
    const float* __restrict__ f1w, const float* __restrict__ f2w)
{
    int idx = blockIdx.x*256 + threadIdx.x;
    if (idx < CC*CC) {
        int r = idx / CC, c = idx % CC;
        float a = 0.f;
        #pragma unroll 4
        for (int k = 0; k < CC; k++) a = fmaf(w2[r*CC+k], f1w[k*CC+c], a);
        g_C1[idx] = a;
    } else if (idx < 2*CC*CC) {
        int t = idx - CC*CC;
        int r = t / CC, c = t % CC;
        float a = 0.f;
        #pragma unroll 4
        for (int k = 0; k < CC; k++) a = fmaf(w2[r*CC+k], f2w[k*CC+c], a);
        g_C2[t] = a;
    } else if (idx < 2*CC*CC + CC) {
        int c = idx - 2*CC*CC;
        float a = 0.f;
        #pragma unroll 4
        for (int k = 0; k < CC; k++) a = fmaf(b2v[k], f1w[k*CC+c], a);
        g_c1[c] = a;
    } else if (idx < 2*CC*CC + 2*CC) {
        int c = idx - 2*CC*CC - CC;
        float a = 0.f;
        #pragma unroll 4
        for (int k = 0; k < CC; k++) a = fmaf(b2v[k], f2w[k*CC+c], a);
        g_c2[c] = a;
    }
}

// ---------------------------------------------------------------------------
// Encoder (fused): hidden = relu(x@w1+b1) -> strided smem (no local memory);
// G1 = hidden@C1 + c1 ; G2 = hidden@C2 + c2.  One thread per point.
// ---------------------------------------------------------------------------
__global__ __launch_bounds__(256) void encoder_kernel(
    const float* __restrict__ x,
    const float* __restrict__ w1, const float* __restrict__ b1v)
{
    extern __shared__ float sh[];          // CC*256 floats = 64KB, strided
    int tid = threadIdx.x;
    int g = blockIdx.x*256 + tid;
    if (g >= BN) return;

    float xr[DD];
    #pragma unroll
    for (int d = 0; d < DD; d++) xr[d] = x[g*DD + d];
    g_pts[g] = make_float4(xr[0], xr[1], xr[2],
                           xr[0]*xr[0] + xr[1]*xr[1] + xr[2]*xr[2]);

    float acc[CC];

    // hidden = relu(x @ w1 + b1) -> smem (thread-private column, no sync)
    {
        const float4* bq = (const float4*)b1v;
        #pragma unroll
        for (int c4 = 0; c4 < CC/4; c4++) {
            float4 bv = bq[c4];
            acc[c4*4+0]=bv.x; acc[c4*4+1]=bv.y; acc[c4*4+2]=bv.z; acc[c4*4+3]=bv.w;
        }
        #pragma unroll
        for (int d = 0; d < DD; d++) {
            float xv = xr[d];
            const float4* wv = (const float4*)(w1 + d*CC);
            #pragma unroll
            for (int c4 = 0; c4 < CC/4; c4++) {
                float4 w = wv[c4];
                acc[c4*4+0] = fmaf(xv, w.x, acc[c4*4+0]);
                acc[c4*4+1] = fmaf(xv, w.y, acc[c4*4+1]);
                acc[c4*4+2] = fmaf(xv, w.z, acc[c4*4+2]);
                acc[c4*4+3] = fmaf(xv, w.w, acc[c4*4+3]);
            }
        }
        #pragma unroll
        for (int c = 0; c < CC; c++) sh[c*256 + tid] = fmaxf(acc[c], 0.f);
    }

    // G1 = hidden @ C1 + c1
    {
        const float4* bq = (const float4*)g_c1;
        #pragma unroll
        for (int c4 = 0; c4 < CC/4; c4++) {
            float4 bv = bq[c4];
            acc[c4*4+0]=bv.x; acc[c4*4+1]=bv.y; acc[c4*4+2]=bv.z; acc[c4*4+3]=bv.w;
        }
        #pragma unroll 1
        for (int j = 0; j < CC; j++) {
            float hv = sh[j*256 + tid];
            const float4* wv = (const float4*)(g_C1 + j*CC);
            #pragma unroll
            for (int c4 = 0; c4 < CC/4; c4++) {
                float4 w = wv[c4];
                acc[c4*4+0] = fmaf(hv, w.x, acc[c4*4+0]);
                acc[c4*4+1] = fmaf(hv, w.y, acc[c4*4+1]);
                acc[c4*4+2] = fmaf(hv, w.z, acc[c4*4+2]);
                acc[c4*4+3] = fmaf(hv, w.w, acc[c4*4+3]);
            }
        }
        float4* o = (float4*)g_G1 + g*(CC/4);
        #pragma unroll
        for (int c4 = 0; c4 < CC/4; c4++)
            o[c4] = make_float4(acc[c4*4+0], acc[c4*4+1], acc[c4*4+2], acc[c4*4+3]);
    }

    // G2 = hidden @ C2 + c2
    {
        const float4* bq = (const float4*)g_c2;
        #pragma unroll
        for (int c4 = 0; c4 < CC/4; c4++) {
            float4 bv = bq[c4];
            acc[c4*4+0]=bv.x; acc[c4*4+1]=bv.y; acc[c4*4+2]=bv.z; acc[c4*4+3]=bv.w;
        }
        #pragma unroll 1
        for (int j = 0; j < CC; j++) {
            float hv = sh[j*256 + tid];
            const float4* wv = (const float4*)(g_C2 + j*CC);
            #pragma unroll
            for (int c4 = 0; c4 < CC/4; c4++) {
                float4 w = wv[c4];
                acc[c4*4+0] = fmaf(hv, w.x, acc[c4*4+0]);
                acc[c4*4+1] = fmaf(hv, w.y, acc[c4*4+1]);
                acc[c4*4+2] = fmaf(hv, w.z, acc[c4*4+2]);
                acc[c4*4+3] = fmaf(hv, w.w, acc[c4*4+3]);
            }
        }
        float4* o = (float4*)g_G2 + g*(CC/4);
        #pragma unroll
        for (int c4 = 0; c4 < CC/4; c4++)
            o[c4] = make_float4(acc[c4*4+0], acc[c4*4+1], acc[c4*4+2], acc[c4*4+3]);
    }
}

// ---------------------------------------------------------------------------
// Compaction: insert smem append-slots into the 32 smem result slots (8x4
// groups, group maxes in regs). Packed u64 (dist_bits<<32 | idx); dist is
// true squared distance clamped >= 0 so u64 order == top_k order.
// ---------------------------------------------------------------------------
__device__ __forceinline__ void compact_smem(
    unsigned long long* tslot, int& cnt, unsigned long long gm[8],
    unsigned long long& worst, float& thr)
{
    #pragma unroll 1
    for (int a = 0; a < cnt; a++) {
        unsigned long long v = tslot[(KK + a) * 256];
        if (v < worst) {
            int gsel = 0; unsigned long long gv = gm[0];
            #pragma unroll
            for (int i = 1; i < 8; i++) if (gm[i] > gv) { gv = gm[i]; gsel = i; }
            int base = gsel * 4;
            unsigned long long s0 = tslot[(base+0)*256];
            unsigned long long s1 = tslot[(base+1)*256];
            unsigned long long s2 = tslot[(base+2)*256];
            unsigned long long s3 = tslot[(base+3)*256];
            int e = 0; unsigned long long ev = s0;
            if (s1 > ev) { ev = s1; e = 1; }
            if (s2 > ev) { ev = s2; e = 2; }
            if (s3 > ev) { ev = s3; e = 3; }
            tslot[(base+e)*256] = v;
            unsigned long long n0 = (e==0)?v:s0, n1 = (e==1)?v:s1;
            unsigned long long n2 = (e==2)?v:s2, n3 = (e==3)?v:s3;
            unsigned long long m01 = n0 > n1 ? n0 : n1;
            unsigned long long m23 = n2 > n3 ? n2 : n3;
            unsigned long long ngm = m01 > m23 ? m01 : m23;
            #pragma unroll
            for (int i = 0; i < 8; i++) if (i == gsel) gm[i] = ngm;
            unsigned long long w8 = gm[0];
            #pragma unroll
            for (int i = 1; i < 8; i++) if (gm[i] > w8) w8 = gm[i];
            worst = w8;
        }
    }
    cnt = 0;
    thr = (worst == ~0ull) ? inf_f()
                           : __uint_as_float((unsigned)(worst >> 32));
}

// ---------------------------------------------------------------------------
// Exact 32-NN, zero local memory, SoA chunks + packed f32x2 distance math.
// Chunk staged as X/Y/Z/W float arrays so ulonglong2 LDS.128 yields ready
// f32-pairs (no packing movs). Per-lane fma sequence identical to the scalar
// version -> bit-identical selection. thr=INF until result slots fill;
// appends use <= so boundary ties survive; compaction warp-synchronized.
// ---------------------------------------------------------------------------
__global__ __launch_bounds__(256) void knn_kernel() {
    extern __shared__ char smemraw[];
    float* sX = (float*)smemraw;
    float* sY = sX + CHUNK;
    float* sZ = sY + CHUNK;
    float* sW = sZ + CHUNK;
    unsigned long long* slots = (unsigned long long*)(smemraw + CHUNK*16);

    int tid = threadIdx.x;
    int b = blockIdx.y;
    const float4* src = g_pts + b*NN;

    int q = blockIdx.x * 256 + tid;
    if (q >= NN) q = NN - 1;              // clamp (ballot safety)

    float4 me = g_pts[b*NN + q];
    float qw = me.w;
    float mx = -2.f*me.x, my = -2.f*me.y, mz = -2.f*me.z;
    const float INF = inf_f();
    unsigned long long qw2, mx2, my2, mz2;
    PK2(qw2, qw, qw); PK2(mx2, mx, mx); PK2(my2, my, my); PK2(mz2, mz, mz);

    unsigned long long* tslot = slots + tid;
    unsigned abase0;
    {
        const void* p = (const void*)(tslot + KK*256);
        unsigned long long l64;
        asm("cvta.to.shared.u64 %0, %1;" : "=l"(l64) : "l"(p));
        abase0 = (unsigned)l64;
    }

    #pragma unroll
    for (int i = 0; i < KK; i++) tslot[i*256] = ~0ull;

    unsigned long long gm[8];
    #pragma unroll
    for (int i = 0; i < 8; i++) gm[i] = ~0ull;
    unsigned long long worst = ~0ull;
    float thr = INF;
    int cnt = 0;

    #pragma unroll 1
    for (int ch = 0; ch < NN/CHUNK; ch++) {          // 4 chunks
        __syncthreads();
        {
            const float4* csrc = src + ch*CHUNK;
            #pragma unroll
            for (int k = 0; k < CHUNK/256; k++) {    // 7 rounds
                int i = tid + k*256;
                float4 c = csrc[i];
                sX[i] = c.x; sY[i] = c.y; sZ[i] = c.z; sW[i] = c.w;
            }
            int i = tid + (CHUNK/256)*256;           // remainder (208)
            if (i < CHUNK) {
                float4 c = csrc[i];
                sX[i] = c.x; sY[i] = c.y; sZ[i] = c.z; sW[i] = c.w;
            }
        }
        __syncthreads();

        int jb = ch*CHUNK;
        #pragma unroll 1
        for (int jo = 0; jo < CHUNK/40; jo++) {      // 50 rounds x 40 cands
            #pragma unroll 1
            for (int gi = 0; gi < 5; gi++) {
                int j0 = jo*40 + gi*8;
                // SoA pair loads: 2x LDS.128 per array = 4 f32-pairs each
                ulonglong2 xv0 = *(const ulonglong2*)(sX + j0);
                ulonglong2 xv1 = *(const ulonglong2*)(sX + j0 + 4);
                ulonglong2 yv0 = *(const ulonglong2*)(sY + j0);
                ulonglong2 yv1 = *(const ulonglong2*)(sY + j0 + 4);
                ulonglong2 zv0 = *(const ulonglong2*)(sZ + j0);
                ulonglong2 zv1 = *(const ulonglong2*)(sZ + j0 + 4);
                ulonglong2 wv0 = *(const ulonglong2*)(sW + j0);
                ulonglong2 wv1 = *(const ulonglong2*)(sW + j0 + 4);
                unsigned long long xp[4] = {xv0.x, xv0.y, xv1.x, xv1.y};
                unsigned long long yp[4] = {yv0.x, yv0.y, yv1.x, yv1.y};
                unsigned long long zp[4] = {zv0.x, zv0.y, zv1.x, zv1.y};
                unsigned long long wp[4] = {wv0.x, wv0.y, wv1.x, wv1.y};
                float s[8];
                #pragma unroll
                for (int p = 0; p < 4; p++) {
                    unsigned long long d;
                    ADD2(d, wp[p], qw2);             // |pj|^2 + |pi|^2 (x2)
                    FMA2(d, xp[p], mx2, d);
                    FMA2(d, yp[p], my2, d);
                    FMA2(d, zp[p], mz2, d);
                    float lo, hi;
                    UPK2(lo, hi, d);
                    s[p*2+0] = fmaxf(lo, 0.f);       // true sq-dist, >= 0
                    s[p*2+1] = fmaxf(hi, 0.f);
                }
                int e0 = (s[0] <= thr) ? 1 : 0;
                int e1 = (s[1] <= thr) ? 1 : 0;
                int e2 = (s[2] <= thr) ? 1 : 0;
                int e3 = (s[3] <= thr) ? 1 : 0;
                int e4 = (s[4] <= thr) ? 1 : 0;
                int e5 = (s[5] <= thr) ? 1 : 0;
                int e6 = (s[6] <= thr) ? 1 : 0;
                int e7 = (s[7] <= thr) ? 1 : 0;
                int t01 = e0+e1, t23 = e2+e3, t45 = e4+e5, t67 = e6+e7;
                int t03 = t01+t23, t47 = t45+t67;
                int o1 = e0, o2 = t01, o3 = t01+e2, o4 = t03;
                int o5 = t03+e4, o6 = t03+t45, o7 = t03+t45+e6;
                int tot = t03 + t47;
                unsigned rowa = abase0 + (unsigned)cnt * 2048u;
                #pragma unroll
                for (int u = 0; u < 8; u++) {
                    int off;
                    switch (u) {
                        case 0: off = 0;  break;
                        case 1: off = o1; break;
                        case 2: off = o2; break;
                        case 3: off = o3; break;
                        case 4: off = o4; break;
                        case 5: off = o5; break;
                        case 6: off = o6; break;
                        default: off = o7; break;
                    }
                    unsigned addr = rowa + (unsigned)off * 2048u;
                    unsigned long long pk =
                        ((unsigned long long)__float_as_uint(s[u]) << 32)
                        | (unsigned)(jb + j0 + u);
                    asm volatile(
                        "{\n\t"
                        ".reg .pred p;\n\t"
                        "setp.le.f32 p, %0, %1;\n\t"
                        "@p st.shared.b64 [%2], %3;\n\t"
                        "}"
                        :: "f"(s[u]), "f"(thr), "r"(addr), "l"(pk)
                        : "memory");
                }
                cnt += tot;
            }
            if (__any_sync(0xffffffffu, cnt >= CAP - 40)) {
                compact_smem(tslot, cnt, gm, worst, thr);
            }
        }
    }

    compact_smem(tslot, cnt, gm, worst, thr);   // final flush

    int* o = g_idx + (b*NN + q)*KK;
    #pragma unroll 1
    for (int i = 0; i < KK; i++)
        o[i] = (int)(unsigned)tslot[i*256];
}

// ---------------------------------------------------------------------------
// Fuse (both branches) + classifier. msg = relu(G[nbr]-G[i]+b); max over K;
// fused = m1+m2; then 64->32->13 MLP. 4 points/block, 64 channel-threads.
// ---------------------------------------------------------------------------
__global__ __launch_bounds__(256) void fuse_kernel(
    const float* __restrict__ f1b, const float* __restrict__ f2b,
    const float* __restrict__ cw1, const float* __restrict__ cb1,
    const float* __restrict__ cw2, const float* __restrict__ cb2,
    float* __restrict__ out)
{
    __shared__ float sfused[4][CC];
    __shared__ float shid[4][CC/2];
    __shared__ int   sidx[4][KK];

    int tid = threadIdx.x;
    int p = tid >> 6, c = tid & 63;
    int g = blockIdx.x*4 + p;

    if (c < KK) sidx[p][c] = g_idx[g*KK + c];
    __syncthreads();

    int b = g / NN;
    int rowbase = b*NN;

    float g1i = g_G1[g*CC + c];
    float g2i = g_G2[g*CC + c];
    float bb1 = f1b[c] - g1i;
    float bb2 = f2b[c] - g2i;
    float m1 = 0.f, m2 = 0.f;
    #pragma unroll 8
    for (int k = 0; k < KK; k++) {
        int j = sidx[p][k] + rowbase;
        m1 = fmaxf(m1, g_G1[j*CC + c] + bb1);
        m2 = fmaxf(m2, g_G2[j*CC + c] + bb2);
    }
    sfused[p][c] = m1 + m2;
    __syncthreads();

    if (c < CC/2) {
        float a = cb1[c];
        #pragma unroll
        for (int u = 0; u < CC; u++) a = fmaf(sfused[p][u], cw1[u*(CC/2) + c], a);
        shid[p][c] = fmaxf(a, 0.f);
    }
    __syncthreads();

    if (c < NCLS) {
        float a = cb2[c];
        #pragma unroll
        for (int u = 0; u < CC/2; u++) a = fmaf(shid[p][u], cw2[u*NCLS + c], a);
        out[g*NCLS + c] = a;
    }
}

extern "C" void kernel_launch(void* const* d_in, const int* in_sizes, int n_in,
                              void* d_out, int out_size) {
    const float* x      = (const float*)d_in[0];
    const float* enc_w1 = (const float*)d_in[1];
    const float* enc_b1 = (const float*)d_in[2];
    const float* enc_w2 = (const float*)d_in[3];
    const float* enc_b2 = (const float*)d_in[4];
    const float* f1_w   = (const float*)d_in[5];
    const float* f1_b   = (const float*)d_in[6];
    const float* f2_w   = (const float*)d_in[7];
    const float* f2_b   = (const float*)d_in[8];
    const float* cls_w1 = (const float*)d_in[9];
    const float* cls_b1 = (const float*)d_in[10];
    const float* cls_w2 = (const float*)d_in[11];
    const float* cls_b2 = (const float*)d_in[12];

    precompute_kernel<<<(2*CC*CC + 2*CC + 255)/256, 256>>>(enc_w2, enc_b2,
                                                           f1_w, f2_w);

    const int enc_smem = CC * 256 * (int)sizeof(float);   // 65536
    cudaFuncSetAttribute(encoder_kernel,
                         cudaFuncAttributeMaxDynamicSharedMemorySize, enc_smem);
    encoder_kernel<<<(BN + 255)/256, 256, enc_smem>>>(x, enc_w1, enc_b1);

    const int knn_smem = CHUNK*16 + NSLOT*256*8;   // 32768 + 180224 = 212992
    cudaFuncSetAttribute(knn_kernel, cudaFuncAttributeMaxDynamicSharedMemorySize,
                         knn_smem);
    dim3 kg((NN + 255)/256, BB);
    knn_kernel<<<kg, 256, knn_smem>>>();

    fuse_kernel<<<BN/4, 256>>>(f1_b, f2_b, cls_w1, cls_b1, cls_w2, cls_b2,
                               (float*)d_out);
}